// round 11
// baseline (speedup 1.0000x reference)
#include <cuda_runtime.h>

#define Hh 128
#define Ww 128
#define HW 16384
#define Bb 4
#define Cin 64
#define Cout 64

// scratch (device globals — no allocation)
__device__ float g_om[4 * 27 * HW];     // offset/mask conv output
__device__ float g_conv[4 * 64 * HW];   // deform conv output (pre-BN)
__device__ float g_wt[576 * 64];        // transposed deform weights [ck][o]
__device__ float g_stats[128];          // [0:64) sum, [64:128) sumsq

// dynamic smem layout (bytes):
//   Vs     @ 0      : 72*128 floats = 36864
//   ws     @ 36864  : 72*64  floats = 18432
//   s_pack @ 55296  : 1152   ints   = 4608
//   s_w4   @ 59904  : 1152   float4 = 18432
//   red_s  @ 78336  : 256 floats, red_q @ 79360 : 256 floats
#define DEFORM_SMEM 80384

// ---------------------------------------------------------------------------
__global__ void zero_stats_kernel() {
    if (threadIdx.x < 128) g_stats[threadIdx.x] = 0.f;
}

// ---------------------------------------------------------------------------
__global__ __launch_bounds__(256) void wt_transpose_kernel(
        const float* __restrict__ wgt) {
    int idx = blockIdx.x * 256 + threadIdx.x;   // 36864 total
    if (idx < 576 * 64) {
        int o  = idx / 576;
        int ck = idx % 576;
        g_wt[ck * 64 + o] = wgt[idx];
    }
}

// ---------------------------------------------------------------------------
// Offset/mask conv (unchanged).
__global__ __launch_bounds__(128) void offset_conv_kernel(
        const float* __restrict__ x,
        const float* __restrict__ ow,
        const float* __restrict__ ob) {
    __shared__ __align__(16) float sw[32 * 9 * 28];   // 32.25 KB
    const int tx = threadIdx.x & 15;
    const int ty = threadIdx.x >> 4;
    const int w = blockIdx.x * 16 + tx;
    const int h = blockIdx.y * 8 + ty;
    const int b = blockIdx.z;

    float acc[28];
#pragma unroll
    for (int i = 0; i < 28; i++) acc[i] = 0.f;

    for (int cc = 0; cc < 64; cc += 32) {
        __syncthreads();
        for (int r = threadIdx.x; r < 288; r += 128) sw[r * 28 + 27] = 0.f;
        for (int j = threadIdx.x; j < 27 * 288; j += 128) {
            int oc = j / 288;
            int r  = j - oc * 288;               // cl*9 + tap
            sw[r * 28 + oc] = ow[oc * 576 + cc * 9 + r];
        }
        __syncthreads();
        for (int cl = 0; cl < 32; cl++) {
            const float* xb = x + ((size_t)(b * 64 + cc + cl)) * HW;
            float xv[9];
#pragma unroll
            for (int ky = 0; ky < 3; ky++)
#pragma unroll
                for (int kx = 0; kx < 3; kx++) {
                    int yy = h - 1 + ky, xx = w - 1 + kx;
                    xv[ky * 3 + kx] =
                        ((unsigned)yy < 128u && (unsigned)xx < 128u) ? xb[yy * 128 + xx] : 0.f;
                }
#pragma unroll
            for (int tap = 0; tap < 9; tap++) {
                float v = xv[tap];
                const float4* wp = (const float4*)&sw[(cl * 9 + tap) * 28];
#pragma unroll
                for (int q = 0; q < 7; q++) {
                    float4 wv = wp[q];
                    acc[q * 4 + 0] += v * wv.x;
                    acc[q * 4 + 1] += v * wv.y;
                    acc[q * 4 + 2] += v * wv.z;
                    acc[q * 4 + 3] += v * wv.w;
                }
            }
        }
    }
    size_t base = (size_t)b * 27 * HW + h * 128 + w;
#pragma unroll
    for (int oc = 0; oc < 27; oc++)
        g_om[base + (size_t)oc * HW] = acc[oc] + ob[oc];
}

// ---------------------------------------------------------------------------
// Deformable conv v3: full-row tile (128 px x 64 oc), 256 threads, dyn smem.
//   Thread = (oc lane 0..31 -> o, o+32) x (warp 0..7 -> 16-px group).
//   Per ckl per warp: 2 scalar w LDS + 4 broadcast LDS.128 -> 32 FFMA.
__global__ __launch_bounds__(256) void deform_kernel(
        const float* __restrict__ x,
        const float* __restrict__ bias) {
    extern __shared__ char dynsmem[];
    float*  Vs     = (float*)dynsmem;                    // [72][128]
    float*  ws     = (float*)(dynsmem + 36864);          // [72][64]
    int*    s_pack = (int*)(dynsmem + 55296);            // [1152]
    float4* s_w4   = (float4*)(dynsmem + 59904);         // [1152]
    float*  red_s  = (float*)(dynsmem + 78336);          // [256]
    float*  red_q  = (float*)(dynsmem + 79360);          // [256]

    const int t = threadIdx.x;
    const int h = blockIdx.x;
    const int b = blockIdx.y;

    // phase 0: per-(tap, pixel) packed clamped addr + folded corner weights
    for (int idx = t; idx < 1152; idx += 256) {
        int p = idx & 127, k = idx >> 7;
        size_t omb = (size_t)b * 27 * HW + h * 128 + p;
        float dy = g_om[omb + (size_t)(2 * k) * HW];
        float dx = g_om[omb + (size_t)(2 * k + 1) * HW];
        float ml = g_om[omb + (size_t)(18 + k) * HW];
        float ys = (float)(h - 1 + k / 3) + dy;
        float xs = (float)(p - 1 + (k % 3)) + dx;
        float y0f = floorf(ys), x0f = floorf(xs);
        int y0 = (int)y0f, x0 = (int)x0f;
        float fy = ys - y0f, fx = xs - x0f;
        float m = 1.f / (1.f + expf(-ml));
        bool vy0 = (unsigned)y0 < 128u, vy1 = (unsigned)(y0 + 1) < 128u;
        bool vx0 = (unsigned)x0 < 128u, vx1 = (unsigned)(x0 + 1) < 128u;
        int yc0 = min(max(y0, 0), 127),     xc0 = min(max(x0, 0), 127);
        int yc1 = min(max(y0 + 1, 0), 127), xc1 = min(max(x0 + 1, 0), 127);
        s_pack[idx] = (yc0 * 128 + xc0) | ((xc1 - xc0) << 14) | ((yc1 - yc0) << 15);
        float wy0 = 1.f - fy, wx0 = 1.f - fx;
        float4 wv;
        wv.x = wy0 * wx0 * m * (float)(vy0 && vx0);
        wv.y = wy0 * fx  * m * (float)(vy0 && vx1);
        wv.z = fy  * wx0 * m * (float)(vy1 && vx0);
        wv.w = fy  * fx  * m * (float)(vy1 && vx1);
        s_w4[idx] = wv;
    }
    __syncthreads();

    const int o  = t & 31;     // oc pair (o, o+32)
    const int pg = t >> 5;     // 16-px group
    float acc1[16], acc2[16];
#pragma unroll
    for (int i = 0; i < 16; i++) { acc1[i] = 0.f; acc2[i] = 0.f; }

    const int pbase = t & 127;     // gather pixel (thread-constant)
    const int ckl0  = t >> 7;      // gather ckl start (0 or 1)

    for (int c0 = 0; c0 < 64; c0 += 8) {
        // stage weights: float4 copy of g_wt rows [c0*9 .. c0*9+72)
        {
            const float4* src = (const float4*)(g_wt + (size_t)c0 * 9 * 64);
            float4* dst = (float4*)ws;
            for (int j = t; j < 72 * 64 / 4; j += 256) dst[j] = src[j];
        }
        // gather V[ckl][p]: 9216 items, 36 per thread, ckl steps by 2
        const float* xb_base = x + ((size_t)(b * 64 + c0)) * HW;
#pragma unroll 4
        for (int j = 0; j < 36; j++) {
            int ckl = ckl0 + 2 * j;
            int c   = ckl / 9;
            int ci  = (ckl - 9 * c) * 128 + pbase;
            int pack = s_pack[ci];
            float4 wv = s_w4[ci];
            int a00 = pack & 16383;
            int dxi = (pack >> 14) & 1;
            int dyi = (pack >> 15) << 7;          // 0 or 128
            const float* xb = xb_base + (size_t)c * HW;
            float v00 = xb[a00];
            float v01 = xb[a00 + dxi];
            float v10 = xb[a00 + dyi];
            float v11 = xb[a00 + dyi + dxi];
            Vs[ckl * 128 + pbase] = wv.x * v00 + wv.y * v01 + wv.z * v10 + wv.w * v11;
        }
        __syncthreads();
        // GEMM: 2 oc x 16 px per thread
#pragma unroll 2
        for (int ckl = 0; ckl < 72; ckl++) {
            float w1 = ws[ckl * 64 + o];
            float w2 = ws[ckl * 64 + o + 32];
            const float4* vp = (const float4*)&Vs[ckl * 128 + pg * 16];
            float4 v0 = vp[0], v1 = vp[1], v2 = vp[2], v3 = vp[3];
            acc1[0]  += w1 * v0.x;  acc1[1]  += w1 * v0.y;
            acc1[2]  += w1 * v0.z;  acc1[3]  += w1 * v0.w;
            acc1[4]  += w1 * v1.x;  acc1[5]  += w1 * v1.y;
            acc1[6]  += w1 * v1.z;  acc1[7]  += w1 * v1.w;
            acc1[8]  += w1 * v2.x;  acc1[9]  += w1 * v2.y;
            acc1[10] += w1 * v2.z;  acc1[11] += w1 * v2.w;
            acc1[12] += w1 * v3.x;  acc1[13] += w1 * v3.y;
            acc1[14] += w1 * v3.z;  acc1[15] += w1 * v3.w;
            acc2[0]  += w2 * v0.x;  acc2[1]  += w2 * v0.y;
            acc2[2]  += w2 * v0.z;  acc2[3]  += w2 * v0.w;
            acc2[4]  += w2 * v1.x;  acc2[5]  += w2 * v1.y;
            acc2[6]  += w2 * v1.z;  acc2[7]  += w2 * v1.w;
            acc2[8]  += w2 * v2.x;  acc2[9]  += w2 * v2.y;
            acc2[10] += w2 * v2.z;  acc2[11] += w2 * v2.w;
            acc2[12] += w2 * v3.x;  acc2[13] += w2 * v3.y;
            acc2[14] += w2 * v3.z;  acc2[15] += w2 * v3.w;
        }
        __syncthreads();
    }

    // epilogue: bias + vectorized store + fused BN partial sums
    float bv1 = bias[o], bv2 = bias[o + 32];
    float ps1 = 0.f, pq1 = 0.f, ps2 = 0.f, pq2 = 0.f;
    {
        size_t base1 = ((size_t)(b * 64 + o) * 128 + h) * 128 + pg * 16;
        size_t base2 = ((size_t)(b * 64 + o + 32) * 128 + h) * 128 + pg * 16;
        float4 r;
#pragma unroll
        for (int q = 0; q < 4; q++) {
            float v0 = acc1[q * 4 + 0] + bv1;
            float v1 = acc1[q * 4 + 1] + bv1;
            float v2 = acc1[q * 4 + 2] + bv1;
            float v3 = acc1[q * 4 + 3] + bv1;
            r.x = v0; r.y = v1; r.z = v2; r.w = v3;
            *(float4*)&g_conv[base1 + q * 4] = r;
            ps1 += v0 + v1 + v2 + v3;
            pq1 += v0 * v0 + v1 * v1 + v2 * v2 + v3 * v3;
            v0 = acc2[q * 4 + 0] + bv2;
            v1 = acc2[q * 4 + 1] + bv2;
            v2 = acc2[q * 4 + 2] + bv2;
            v3 = acc2[q * 4 + 3] + bv2;
            r.x = v0; r.y = v1; r.z = v2; r.w = v3;
            *(float4*)&g_conv[base2 + q * 4] = r;
            ps2 += v0 + v1 + v2 + v3;
            pq2 += v0 * v0 + v1 * v1 + v2 * v2 + v3 * v3;
        }
    }
    // channels 0..31
    red_s[t] = ps1; red_q[t] = pq1;
    __syncthreads();
    if (t < 32) {
        float s = 0.f, q = 0.f;
#pragma unroll
        for (int j = 0; j < 8; j++) { s += red_s[t + 32 * j]; q += red_q[t + 32 * j]; }
        atomicAdd(&g_stats[t], s);
        atomicAdd(&g_stats[64 + t], q);
    }
    __syncthreads();
    // channels 32..63
    red_s[t] = ps2; red_q[t] = pq2;
    __syncthreads();
    if (t < 32) {
        float s = 0.f, q = 0.f;
#pragma unroll
        for (int j = 0; j < 8; j++) { s += red_s[t + 32 * j]; q += red_q[t + 32 * j]; }
        atomicAdd(&g_stats[32 + t], s);
        atomicAdd(&g_stats[96 + t], q);
    }
}

// ---------------------------------------------------------------------------
// Finalize: per-channel affine + ReLU, float4 vectorized (HBM-bound).
__global__ __launch_bounds__(256) void finalize_kernel(
        const float* __restrict__ gamma, const float* __restrict__ beta,
        float* __restrict__ out) {
    __shared__ float s_scale[64], s_shift[64];
    if (threadIdx.x < 64) {
        const float invN = 1.f / 65536.f;   // B*H*W = 4*128*128
        int o = threadIdx.x;
        float mean = g_stats[o] * invN;
        float var  = g_stats[64 + o] * invN - mean * mean;
        float sc = rsqrtf(var + 1e-5f) * gamma[o];
        s_scale[o] = sc;
        s_shift[o] = beta[o] - mean * sc;
    }
    __syncthreads();
    const float4* cv = (const float4*)g_conv;
    float4* ov = (float4*)out;
    const size_t total4 = (size_t)4 * 64 * HW / 4;   // 1,048,576 float4s
    for (size_t i4 = (size_t)blockIdx.x * 256 + threadIdx.x; i4 < total4;
         i4 += (size_t)gridDim.x * 256) {
        int o = (int)((i4 >> 12) & 63);              // 4096 float4s per channel
        float sc = s_scale[o], sh = s_shift[o];
        float4 v = cv[i4];
        float4 r;
        r.x = fmaxf(v.x * sc + sh, 0.f);
        r.y = fmaxf(v.y * sc + sh, 0.f);
        r.z = fmaxf(v.z * sc + sh, 0.f);
        r.w = fmaxf(v.w * sc + sh, 0.f);
        ov[i4] = r;
    }
}

// ---------------------------------------------------------------------------
extern "C" void kernel_launch(void* const* d_in, const int* in_sizes, int n_in,
                              void* d_out, int out_size) {
    const float* x     = (const float*)d_in[0];
    const float* ow    = (const float*)d_in[1];
    const float* ob    = (const float*)d_in[2];
    const float* wgt   = (const float*)d_in[3];
    const float* bias  = (const float*)d_in[4];
    const float* gamma = (const float*)d_in[5];
    const float* beta  = (const float*)d_in[6];
    float* out = (float*)d_out;

    cudaFuncSetAttribute(deform_kernel,
                         cudaFuncAttributeMaxDynamicSharedMemorySize, DEFORM_SMEM);

    zero_stats_kernel<<<1, 128>>>();
    wt_transpose_kernel<<<144, 256>>>(wgt);
    offset_conv_kernel<<<dim3(8, 16, 4), 128>>>(x, ow, ob);
    deform_kernel<<<dim3(128, 4), 256, DEFORM_SMEM>>>(x, bias);
    finalize_kernel<<<2048, 256>>>(gamma, beta, out);
}

// round 16
// speedup vs baseline: 1.3312x; 1.3312x over previous
#include <cuda_runtime.h>

#define Hh 128
#define Ww 128
#define HW 16384
#define Bb 4
#define Cin 64
#define Cout 64

// scratch (device globals — no allocation)
__device__ float g_om[4 * 27 * HW];     // offset/mask conv output
__device__ float g_conv[4 * 64 * HW];   // deform conv output (pre-BN)
__device__ float g_wt[576 * 64];        // transposed deform weights [ck][o]
__device__ float g_stats[128];          // [0:64) sum, [64:128) sumsq

// ---------------------------------------------------------------------------
__global__ void zero_stats_kernel() {
    if (threadIdx.x < 128) g_stats[threadIdx.x] = 0.f;
}

// ---------------------------------------------------------------------------
__global__ __launch_bounds__(256) void wt_transpose_kernel(
        const float* __restrict__ wgt) {
    int idx = blockIdx.x * 256 + threadIdx.x;   // 36864 total
    if (idx < 576 * 64) {
        int o  = idx / 576;
        int ck = idx % 576;
        g_wt[ck * 64 + o] = wgt[idx];
    }
}

// ---------------------------------------------------------------------------
// Offset/mask conv (unchanged).
__global__ __launch_bounds__(128) void offset_conv_kernel(
        const float* __restrict__ x,
        const float* __restrict__ ow,
        const float* __restrict__ ob) {
    __shared__ __align__(16) float sw[32 * 9 * 28];   // 32.25 KB
    const int tx = threadIdx.x & 15;
    const int ty = threadIdx.x >> 4;
    const int w = blockIdx.x * 16 + tx;
    const int h = blockIdx.y * 8 + ty;
    const int b = blockIdx.z;

    float acc[28];
#pragma unroll
    for (int i = 0; i < 28; i++) acc[i] = 0.f;

    for (int cc = 0; cc < 64; cc += 32) {
        __syncthreads();
        for (int r = threadIdx.x; r < 288; r += 128) sw[r * 28 + 27] = 0.f;
        for (int j = threadIdx.x; j < 27 * 288; j += 128) {
            int oc = j / 288;
            int r  = j - oc * 288;               // cl*9 + tap
            sw[r * 28 + oc] = ow[oc * 576 + cc * 9 + r];
        }
        __syncthreads();
        for (int cl = 0; cl < 32; cl++) {
            const float* xb = x + ((size_t)(b * 64 + cc + cl)) * HW;
            float xv[9];
#pragma unroll
            for (int ky = 0; ky < 3; ky++)
#pragma unroll
                for (int kx = 0; kx < 3; kx++) {
                    int yy = h - 1 + ky, xx = w - 1 + kx;
                    xv[ky * 3 + kx] =
                        ((unsigned)yy < 128u && (unsigned)xx < 128u) ? xb[yy * 128 + xx] : 0.f;
                }
#pragma unroll
            for (int tap = 0; tap < 9; tap++) {
                float v = xv[tap];
                const float4* wp = (const float4*)&sw[(cl * 9 + tap) * 28];
#pragma unroll
                for (int q = 0; q < 7; q++) {
                    float4 wv = wp[q];
                    acc[q * 4 + 0] += v * wv.x;
                    acc[q * 4 + 1] += v * wv.y;
                    acc[q * 4 + 2] += v * wv.z;
                    acc[q * 4 + 3] += v * wv.w;
                }
            }
        }
    }
    size_t base = (size_t)b * 27 * HW + h * 128 + w;
#pragma unroll
    for (int oc = 0; oc < 27; oc++)
        g_om[base + (size_t)oc * HW] = acc[oc] + ob[oc];
}

// ---------------------------------------------------------------------------
// Deformable conv v5: 64 px x 64 oc tile (round-9 GEMM mapping, measured),
// gather amortizes (tap,pixel) metadata over all 8 channels of a chunk.
__global__ __launch_bounds__(256) void deform_kernel(
        const float* __restrict__ x,
        const float* __restrict__ bias) {
    __shared__ int    s_pack[576];                      // 2.25 KB  [k*64+p]
    __shared__ __align__(16) float4 s_w4[576];          // 9 KB
    __shared__ __align__(16) float Vs[72 * 64];         // 18 KB
    __shared__ __align__(16) float ws[72 * 64];         // 18 KB
    __shared__ float red_s[256], red_q[256];            // 2 KB

    const int t  = threadIdx.x;
    const int b  = blockIdx.z;
    const int h  = blockIdx.y;
    const int w0 = blockIdx.x * 64;

    // phase 0: per-(tap, pixel) packed clamped addr + folded corner weights
    for (int idx = t; idx < 576; idx += 256) {
        int p = idx & 63, k = idx >> 6;
        size_t omb = (size_t)b * 27 * HW + h * 128 + (w0 + p);
        float dy = g_om[omb + (size_t)(2 * k) * HW];
        float dx = g_om[omb + (size_t)(2 * k + 1) * HW];
        float ml = g_om[omb + (size_t)(18 + k) * HW];
        float ys = (float)(h - 1 + k / 3) + dy;
        float xs = (float)(w0 + p - 1 + (k % 3)) + dx;
        float y0f = floorf(ys), x0f = floorf(xs);
        int y0 = (int)y0f, x0 = (int)x0f;
        float fy = ys - y0f, fx = xs - x0f;
        float m = 1.f / (1.f + expf(-ml));
        bool vy0 = (unsigned)y0 < 128u, vy1 = (unsigned)(y0 + 1) < 128u;
        bool vx0 = (unsigned)x0 < 128u, vx1 = (unsigned)(x0 + 1) < 128u;
        int yc0 = min(max(y0, 0), 127),     xc0 = min(max(x0, 0), 127);
        int yc1 = min(max(y0 + 1, 0), 127), xc1 = min(max(x0 + 1, 0), 127);
        s_pack[idx] = (yc0 * 128 + xc0) | ((xc1 - xc0) << 14) | ((yc1 - yc0) << 15);
        float wy0 = 1.f - fy, wx0 = 1.f - fx;
        float4 wv;
        wv.x = wy0 * wx0 * m * (float)(vy0 && vx0);
        wv.y = wy0 * fx  * m * (float)(vy0 && vx1);
        wv.z = fy  * wx0 * m * (float)(vy1 && vx0);
        wv.w = fy  * fx  * m * (float)(vy1 && vx1);
        s_w4[idx] = wv;
    }
    __syncthreads();

    const int o  = t & 31;     // oc pair (o, o+32)
    const int pg = t >> 5;     // 8-px group (8 groups x 8 px = 64 px)
    float acc1[8], acc2[8];
#pragma unroll
    for (int i = 0; i < 8; i++) { acc1[i] = 0.f; acc2[i] = 0.f; }

    for (int c0 = 0; c0 < 64; c0 += 8) {
        // stage weights: float4 copy of g_wt rows [c0*9 .. c0*9+72)
        {
            const float4* src = (const float4*)(g_wt + (size_t)c0 * 9 * 64);
            float4* dst = (float4*)ws;
            for (int j = t; j < 72 * 64 / 4; j += 256) dst[j] = src[j];
        }
        // gather: 576 (tap,pixel) items; each thread loads metadata once and
        // produces all 8 channels of the chunk for its item.
#pragma unroll
        for (int jj = 0; jj < 3; jj++) {
            int idx = t + 256 * jj;
            if (idx < 576) {
                int p = idx & 63, k = idx >> 6;
                int pack = s_pack[idx];
                float4 wv = s_w4[idx];
                int a00 = pack & 16383;
                int dxi = (pack >> 14) & 1;
                int dyi = (pack >> 15) << 7;          // 0 or 128
                const float* xb = x + ((size_t)(b * 64 + c0)) * HW;
                float* vdst = &Vs[k * 64 + p];
#pragma unroll
                for (int c = 0; c < 8; c++) {
                    float v00 = xb[a00];
                    float v01 = xb[a00 + dxi];
                    float v10 = xb[a00 + dyi];
                    float v11 = xb[a00 + dyi + dxi];
                    vdst[c * 9 * 64] =
                        wv.x * v00 + wv.y * v01 + wv.z * v10 + wv.w * v11;
                    xb += HW;
                }
            }
        }
        __syncthreads();
        // GEMM: 2 oc x 8 px per thread (round-9 mapping, measured 215us)
#pragma unroll 4
        for (int ckl = 0; ckl < 72; ckl++) {
            float w1 = ws[ckl * 64 + o];
            float w2 = ws[ckl * 64 + o + 32];
            float4 va = *(const float4*)&Vs[ckl * 64 + pg * 8];
            float4 vb = *(const float4*)&Vs[ckl * 64 + pg * 8 + 4];
            acc1[0] += w1 * va.x;  acc1[1] += w1 * va.y;
            acc1[2] += w1 * va.z;  acc1[3] += w1 * va.w;
            acc1[4] += w1 * vb.x;  acc1[5] += w1 * vb.y;
            acc1[6] += w1 * vb.z;  acc1[7] += w1 * vb.w;
            acc2[0] += w2 * va.x;  acc2[1] += w2 * va.y;
            acc2[2] += w2 * va.z;  acc2[3] += w2 * va.w;
            acc2[4] += w2 * vb.x;  acc2[5] += w2 * vb.y;
            acc2[6] += w2 * vb.z;  acc2[7] += w2 * vb.w;
        }
        __syncthreads();
    }

    // epilogue: bias + vectorized store + fused BN partial sums
    float bv1 = bias[o], bv2 = bias[o + 32];
    float ps1 = 0.f, pq1 = 0.f, ps2 = 0.f, pq2 = 0.f;
    {
        size_t base1 = ((size_t)(b * 64 + o) * 128 + h) * 128 + w0 + pg * 8;
        size_t base2 = ((size_t)(b * 64 + o + 32) * 128 + h) * 128 + w0 + pg * 8;
        float4 r;
#pragma unroll
        for (int half = 0; half < 2; half++) {
            float v0 = acc1[half * 4 + 0] + bv1;
            float v1 = acc1[half * 4 + 1] + bv1;
            float v2 = acc1[half * 4 + 2] + bv1;
            float v3 = acc1[half * 4 + 3] + bv1;
            r.x = v0; r.y = v1; r.z = v2; r.w = v3;
            *(float4*)&g_conv[base1 + half * 4] = r;
            ps1 += v0 + v1 + v2 + v3;
            pq1 += v0 * v0 + v1 * v1 + v2 * v2 + v3 * v3;
            v0 = acc2[half * 4 + 0] + bv2;
            v1 = acc2[half * 4 + 1] + bv2;
            v2 = acc2[half * 4 + 2] + bv2;
            v3 = acc2[half * 4 + 3] + bv2;
            r.x = v0; r.y = v1; r.z = v2; r.w = v3;
            *(float4*)&g_conv[base2 + half * 4] = r;
            ps2 += v0 + v1 + v2 + v3;
            pq2 += v0 * v0 + v1 * v1 + v2 * v2 + v3 * v3;
        }
    }
    // channels 0..31
    red_s[t] = ps1; red_q[t] = pq1;
    __syncthreads();
    if (t < 32) {
        float s = 0.f, q = 0.f;
#pragma unroll
        for (int j = 0; j < 8; j++) { s += red_s[t + 32 * j]; q += red_q[t + 32 * j]; }
        atomicAdd(&g_stats[t], s);
        atomicAdd(&g_stats[64 + t], q);
    }
    __syncthreads();
    // channels 32..63
    red_s[t] = ps2; red_q[t] = pq2;
    __syncthreads();
    if (t < 32) {
        float s = 0.f, q = 0.f;
#pragma unroll
        for (int j = 0; j < 8; j++) { s += red_s[t + 32 * j]; q += red_q[t + 32 * j]; }
        atomicAdd(&g_stats[32 + t], s);
        atomicAdd(&g_stats[96 + t], q);
    }
}

// ---------------------------------------------------------------------------
// Finalize: per-channel affine + ReLU, float4 vectorized (HBM-bound).
__global__ __launch_bounds__(256) void finalize_kernel(
        const float* __restrict__ gamma, const float* __restrict__ beta,
        float* __restrict__ out) {
    __shared__ float s_scale[64], s_shift[64];
    if (threadIdx.x < 64) {
        const float invN = 1.f / 65536.f;   // B*H*W = 4*128*128
        int o = threadIdx.x;
        float mean = g_stats[o] * invN;
        float var  = g_stats[64 + o] * invN - mean * mean;
        float sc = rsqrtf(var + 1e-5f) * gamma[o];
        s_scale[o] = sc;
        s_shift[o] = beta[o] - mean * sc;
    }
    __syncthreads();
    const float4* cv = (const float4*)g_conv;
    float4* ov = (float4*)out;
    const size_t total4 = (size_t)4 * 64 * HW / 4;   // 1,048,576 float4s
    for (size_t i4 = (size_t)blockIdx.x * 256 + threadIdx.x; i4 < total4;
         i4 += (size_t)gridDim.x * 256) {
        int o = (int)((i4 >> 12) & 63);              // 4096 float4s per channel
        float sc = s_scale[o], sh = s_shift[o];
        float4 v = cv[i4];
        float4 r;
        r.x = fmaxf(v.x * sc + sh, 0.f);
        r.y = fmaxf(v.y * sc + sh, 0.f);
        r.z = fmaxf(v.z * sc + sh, 0.f);
        r.w = fmaxf(v.w * sc + sh, 0.f);
        ov[i4] = r;
    }
}

// ---------------------------------------------------------------------------
extern "C" void kernel_launch(void* const* d_in, const int* in_sizes, int n_in,
                              void* d_out, int out_size) {
    const float* x     = (const float*)d_in[0];
    const float* ow    = (const float*)d_in[1];
    const float* ob    = (const float*)d_in[2];
    const float* wgt   = (const float*)d_in[3];
    const float* bias  = (const float*)d_in[4];
    const float* gamma = (const float*)d_in[5];
    const float* beta  = (const float*)d_in[6];
    float* out = (float*)d_out;

    zero_stats_kernel<<<1, 128>>>();
    wt_transpose_kernel<<<144, 256>>>(wgt);
    offset_conv_kernel<<<dim3(8, 16, 4), 128>>>(x, ow, ob);
    deform_kernel<<<dim3(2, 128, 4), 256>>>(x, bias);
    finalize_kernel<<<2048, 256>>>(gamma, beta, out);
}